// round 10
// baseline (speedup 1.0000x reference)
#include <cuda_runtime.h>
#include <math.h>

// Problem shape (fixed by setup_inputs): pred/target (32,1,1024,1024) f32.
#define Wd   1024
#define Hd   1024
#define Bd   32
#define RPB  8                        // rows per block (finer granularity -> smaller tail)
#define GRPS (Hd / RPB)               // 128 row-groups per image
#define NBLK (Bd * GRPS)              // 4096 blocks
#define NTHR 256                      // 8 warps * 128 cols = 1024 cols

#define NEG_BIG (-1.0e30f)
#define POS_BIG ( 1.0e30f)
#define FULLM 0xFFFFFFFFu
#define NLN2  (-0.69314718055994530942f)

__device__ float        g_partials[NBLK];
__device__ unsigned int g_ticket;     // zero-init; reset by last block

__device__ __forceinline__ float max3(float a, float b, float c) {
    return fmaxf(fmaxf(a, b), c);
}
__device__ __forceinline__ float min3(float a, float b, float c) {
    return fminf(fminf(a, b), c);
}

// Per-row contribution: Sum_i w_i * log2(1-|t_i-p_i|), w_i = 1+2*boundary_i.
// eMax/eMin: this lane's halo-column vertical extremes — on lane 0 the LEFT
// halo column, on lane 31 the RIGHT one (identities at the image border).
__device__ __forceinline__ float row_loss(
    const float4 vmax, const float4 vmin, const float4 t, const float4 p,
    float eMax, float eMin, int lane)
{
    float lMax = __shfl_up_sync(FULLM, vmax.w, 1);
    float lMin = __shfl_up_sync(FULLM, vmin.w, 1);
    float rMax = __shfl_down_sync(FULLM, vmax.x, 1);
    float rMin = __shfl_down_sync(FULLM, vmin.x, 1);
    if (lane == 0)  { lMax = eMax; lMin = eMin; }
    if (lane == 31) { rMax = eMax; rMin = eMin; }

    // boundary indicator: dilated - eroded, exactly 0.0 or 1.0 (binary mask)
    float b0 = max3(lMax,   vmax.x, vmax.y) - min3(lMin,   vmin.x, vmin.y);
    float b1 = max3(vmax.x, vmax.y, vmax.z) - min3(vmin.x, vmin.y, vmin.z);
    float b2 = max3(vmax.y, vmax.z, vmax.w) - min3(vmin.y, vmin.z, vmin.w);
    float b3 = max3(vmax.z, vmax.w, rMax)   - min3(vmin.z, vmin.w, rMin);

    // arg = 1-|t-p| == (t ? p : 1-p) exactly; pred in (1e-6, 1-1e-6) => arg>0.
    float s;
    s  = fmaf(2.0f, b0, 1.0f) * __log2f(1.0f - fabsf(t.x - p.x));
    s += fmaf(2.0f, b1, 1.0f) * __log2f(1.0f - fabsf(t.y - p.y));
    s += fmaf(2.0f, b2, 1.0f) * __log2f(1.0f - fabsf(t.z - p.z));
    s += fmaf(2.0f, b3, 1.0f) * __log2f(1.0f - fabsf(t.w - p.w));
    return s;
}

__global__ __launch_bounds__(NTHR, 5)
void bab_fused(const float* __restrict__ pred, const float* __restrict__ target,
               float* __restrict__ out)
{
    const int tid  = threadIdx.x;
    const int lane = tid & 31;
    const int warp = tid >> 5;

    const int grp = blockIdx.x;
    const int img = grp / GRPS;
    const int y0  = (grp % GRPS) * RPB;

    const int x0 = warp * 128 + lane * 4;     // this thread's 4 columns

    // Merged halo: lane 0 tracks the LEFT halo column, lane 31 the RIGHT one.
    const int xH  = (lane == 0) ? (warp * 128 - 1) : (warp * 128 + 128);
    const bool doH = ((lane == 0) && (xH >= 0)) || ((lane == 31) && (xH < Wd));
    const float eMaxId = NEG_BIG, eMinId = POS_BIG;   // border identities

    const float* __restrict__ tb = target + (size_t)img * Hd * Wd;
    const float* __restrict__ pb = pred   + (size_t)img * Hd * Wd;

    // Rolling register window of target rows: prev (y-1), cur (y).
    // Border rows via index clamp (clamped row == pooling identity).
    const int ypInit = (y0 > 0) ? (y0 - 1) : 0;
    float4 cur  = *(const float4*)(tb + (size_t)y0 * Wd + x0);
    float4 prev = *(const float4*)(tb + (size_t)ypInit * Wd + x0);

    float curH = 0.f, prevH = 0.f;
    if (doH) { curH  = tb[(size_t)y0 * Wd + xH];
               prevH = tb[(size_t)ypInit * Wd + xH]; }

    float acc = 0.0f;

    // Two rows per iteration; pairwise-shared vertical extremes.
    #pragma unroll 2
    for (int r = 0; r < RPB; r += 2) {
        const int y   = y0 + r;
        const int yn1 = y + 1;                             // always < Hd in-block
        const int yn2 = (y + 2 < Hd) ? (y + 2) : (Hd - 1); // clamp -> identity

        // All loads up front (affine, unconditional for the float4s).
        const float4 nextA = *(const float4*)(tb + (size_t)yn1 * Wd + x0);
        const float4 nextB = *(const float4*)(tb + (size_t)yn2 * Wd + x0);
        const float4 pA    = *(const float4*)(pb + (size_t)y   * Wd + x0);
        const float4 pB    = *(const float4*)(pb + (size_t)yn1 * Wd + x0);
        const float nextAH = doH ? tb[(size_t)yn1 * Wd + xH] : 0.f;
        const float nextBH = doH ? tb[(size_t)yn2 * Wd + xH] : 0.f;

        // Shared pair extremes of (cur, nextA).
        float4 pmx, pmn;
        pmx.x = fmaxf(cur.x, nextA.x); pmn.x = fminf(cur.x, nextA.x);
        pmx.y = fmaxf(cur.y, nextA.y); pmn.y = fminf(cur.y, nextA.y);
        pmx.z = fmaxf(cur.z, nextA.z); pmn.z = fminf(cur.z, nextA.z);
        pmx.w = fmaxf(cur.w, nextA.w); pmn.w = fminf(cur.w, nextA.w);

        // Row A vertical extremes: (prev, cur, nextA) = op(prev, pair).
        float4 vmaxA, vminA, vmaxB, vminB;
        vmaxA.x = fmaxf(prev.x, pmx.x); vminA.x = fminf(prev.x, pmn.x);
        vmaxA.y = fmaxf(prev.y, pmx.y); vminA.y = fminf(prev.y, pmn.y);
        vmaxA.z = fmaxf(prev.z, pmx.z); vminA.z = fminf(prev.z, pmn.z);
        vmaxA.w = fmaxf(prev.w, pmx.w); vminA.w = fminf(prev.w, pmn.w);
        // Row B vertical extremes: (cur, nextA, nextB) = op(pair, nextB).
        vmaxB.x = fmaxf(nextB.x, pmx.x); vminB.x = fminf(nextB.x, pmn.x);
        vmaxB.y = fmaxf(nextB.y, pmx.y); vminB.y = fminf(nextB.y, pmn.y);
        vmaxB.z = fmaxf(nextB.z, pmx.z); vminB.z = fminf(nextB.z, pmn.z);
        vmaxB.w = fmaxf(nextB.w, pmx.w); vminB.w = fminf(nextB.w, pmn.w);

        // Halo-column vertical extremes for this lane's halo column.
        const float eMaxA = doH ? max3(prevH, curH, nextAH) : eMaxId;
        const float eMinA = doH ? min3(prevH, curH, nextAH) : eMinId;
        const float eMaxB = doH ? max3(curH, nextAH, nextBH) : eMaxId;
        const float eMinB = doH ? min3(curH, nextAH, nextBH) : eMinId;

        acc += row_loss(vmaxA, vminA, cur,   pA, eMaxA, eMinA, lane);
        acc += row_loss(vmaxB, vminB, nextA, pB, eMaxB, eMinB, lane);

        prev  = nextA;  cur  = nextB;
        prevH = nextAH; curH = nextBH;
    }

    acc *= NLN2;   // one scale: sum of w*log2(arg) -> sum of w*(-ln(arg))

    // ---- Block reduction: warp shuffle, then cross-warp via shared. ----
    #pragma unroll
    for (int off = 16; off > 0; off >>= 1)
        acc += __shfl_down_sync(FULLM, acc, off);

    __shared__ float swarp[NTHR / 32];
    if (lane == 0) swarp[warp] = acc;
    __syncthreads();
    if (tid == 0) {
        float v = 0.0f;
        #pragma unroll
        for (int i = 0; i < NTHR / 32; ++i) v += swarp[i];
        g_partials[blockIdx.x] = v;
    }

    // ---- Last-block fused finalize (deterministic order). ----
    __shared__ bool s_last;
    __threadfence();
    if (tid == 0) {
        unsigned int old = atomicAdd(&g_ticket, 1u);
        s_last = (old == NBLK - 1);
    }
    __syncthreads();

    if (s_last) {
        __shared__ double sd[NTHR];
        double s = 0.0;
        for (int i = tid; i < NBLK; i += NTHR)   // fixed order per thread
            s += (double)g_partials[i];
        sd[tid] = s;
        __syncthreads();
        #pragma unroll
        for (int stride = NTHR / 2; stride > 0; stride >>= 1) {
            if (tid < stride) sd[tid] += sd[tid + stride];
            __syncthreads();
        }
        if (tid == 0) {
            out[0] = (float)(sd[0] / (double)((size_t)Bd * Hd * Wd));
            g_ticket = 0;                        // reset for next launch/replay
        }
    }
}

extern "C" void kernel_launch(void* const* d_in, const int* in_sizes, int n_in,
                              void* d_out, int out_size)
{
    (void)in_sizes; (void)n_in; (void)out_size;
    const float* pred   = (const float*)d_in[0];
    const float* target = (const float*)d_in[1];
    float* out = (float*)d_out;

    bab_fused<<<NBLK, NTHR>>>(pred, target, out);
}

// round 11
// speedup vs baseline: 1.2938x; 1.2938x over previous
#include <cuda_runtime.h>
#include <math.h>

// Problem shape (fixed by setup_inputs): pred/target (32,1,1024,1024) f32.
#define Wd   1024
#define Hd   1024
#define Bd   32
#define RPB  16                       // rows per block (R8-proven granularity)
#define GRPS (Hd / RPB)               // 64 row-groups per image
#define NBLK (Bd * GRPS)              // 2048 blocks
#define NTHR 256                      // 8 warps * 128 cols = 1024 cols

#define FULLM 0xFFFFFFFFu
#define NLN2  (-0.69314718055994530942f)

__device__ float        g_partials[NBLK];
__device__ unsigned int g_ticket;     // zero-init; reset by last block

// Per-row contribution: Sum_i w_i * log2(1-|t_i-p_i|), w_i = 1+2*b_i.
// Binary mask: 3x3-window sum S in [0,9]; boundary b = min(S, 9-S, 1).
// Border rows/cols are handled by DUPLICATING the edge cell (clamp), which
// preserves S==0 <=> all-zero and S==9 <=> all-one exactly.
// c: vertical 3-row column sums for this thread's 4 columns.
// haloSum: vertical 3-sum of this lane's halo column (lane 0 = left, lane 31
// = right); when doH==false (image border) we substitute the thread's own
// edge colsum (duplicate-edge clamp).
__device__ __forceinline__ float row_loss(
    const float4 c, const float4 t, const float4 p,
    float haloSum, bool doH, int lane)
{
    float l = __shfl_up_sync(FULLM, c.w, 1);
    float r = __shfl_down_sync(FULLM, c.x, 1);
    if (lane == 0)  l = doH ? haloSum : c.x;
    if (lane == 31) r = doH ? haloSum : c.w;

    const float S0 = l   + c.x + c.y;
    const float S1 = c.x + c.y + c.z;
    const float S2 = c.y + c.z + c.w;
    const float S3 = c.z + c.w + r;

    const float b0 = fminf(fminf(S0, 9.0f - S0), 1.0f);
    const float b1 = fminf(fminf(S1, 9.0f - S1), 1.0f);
    const float b2 = fminf(fminf(S2, 9.0f - S2), 1.0f);
    const float b3 = fminf(fminf(S3, 9.0f - S3), 1.0f);

    // arg = 1-|t-p| == (t ? p : 1-p) exactly; pred in (1e-6, 1-1e-6) => arg>0.
    float s;
    s  = fmaf(2.0f, b0, 1.0f) * __log2f(1.0f - fabsf(t.x - p.x));
    s += fmaf(2.0f, b1, 1.0f) * __log2f(1.0f - fabsf(t.y - p.y));
    s += fmaf(2.0f, b2, 1.0f) * __log2f(1.0f - fabsf(t.z - p.z));
    s += fmaf(2.0f, b3, 1.0f) * __log2f(1.0f - fabsf(t.w - p.w));
    return s;
}

__global__ __launch_bounds__(NTHR, 5)
void bab_fused(const float* __restrict__ pred, const float* __restrict__ target,
               float* __restrict__ out)
{
    const int tid  = threadIdx.x;
    const int lane = tid & 31;
    const int warp = tid >> 5;

    const int grp = blockIdx.x;
    const int img = grp / GRPS;
    const int y0  = (grp % GRPS) * RPB;

    const int x0 = warp * 128 + lane * 4;     // this thread's 4 columns

    // Merged halo: lane 0 tracks the LEFT halo column, lane 31 the RIGHT one.
    const int xH  = (lane == 0) ? (warp * 128 - 1) : (warp * 128 + 128);
    const bool doH = ((lane == 0) && (xH >= 0)) || ((lane == 31) && (xH < Wd));

    const float* __restrict__ tb = target + (size_t)img * Hd * Wd;
    const float* __restrict__ pb = pred   + (size_t)img * Hd * Wd;

    // Rolling register window of target rows: prev (y-1), cur (y).
    // Border rows via index clamp (duplicate row == pooling/sum identity).
    const int ypInit = (y0 > 0) ? (y0 - 1) : 0;
    float4 cur  = *(const float4*)(tb + (size_t)y0 * Wd + x0);
    float4 prev = *(const float4*)(tb + (size_t)ypInit * Wd + x0);

    float curH = 0.f, prevH = 0.f;
    if (doH) { curH  = tb[(size_t)y0 * Wd + xH];
               prevH = tb[(size_t)ypInit * Wd + xH]; }

    float acc = 0.0f;

    // Two rows per iteration; pairwise-shared vertical SUMS.
    #pragma unroll 2
    for (int r = 0; r < RPB; r += 2) {
        const int y   = y0 + r;
        const int yn1 = y + 1;                             // always < Hd in-block
        const int yn2 = (y + 2 < Hd) ? (y + 2) : (Hd - 1); // clamp -> duplicate

        // All loads up front (affine, unconditional for the float4s).
        const float4 nextA = *(const float4*)(tb + (size_t)yn1 * Wd + x0);
        const float4 nextB = *(const float4*)(tb + (size_t)yn2 * Wd + x0);
        const float4 pA    = *(const float4*)(pb + (size_t)y   * Wd + x0);
        const float4 pB    = *(const float4*)(pb + (size_t)yn1 * Wd + x0);
        const float nextAH = doH ? tb[(size_t)yn1 * Wd + xH] : 0.f;
        const float nextBH = doH ? tb[(size_t)yn2 * Wd + xH] : 0.f;

        // Shared pair sums of (cur, nextA).
        float4 ps;
        ps.x = cur.x + nextA.x;
        ps.y = cur.y + nextA.y;
        ps.z = cur.z + nextA.z;
        ps.w = cur.w + nextA.w;

        // Vertical 3-row column sums.
        float4 cA, cB;
        cA.x = prev.x + ps.x;  cB.x = ps.x + nextB.x;
        cA.y = prev.y + ps.y;  cB.y = ps.y + nextB.y;
        cA.z = prev.z + ps.z;  cB.z = ps.z + nextB.z;
        cA.w = prev.w + ps.w;  cB.w = ps.w + nextB.w;

        // Halo-column vertical sums (edge lanes only; unused otherwise).
        const float hsA = prevH + curH + nextAH;
        const float hsB = curH + nextAH + nextBH;

        acc += row_loss(cA, cur,   pA, hsA, doH, lane);
        acc += row_loss(cB, nextA, pB, hsB, doH, lane);

        prev  = nextA;  cur  = nextB;
        prevH = nextAH; curH = nextBH;
    }

    acc *= NLN2;   // one scale: sum of w*log2(arg) -> sum of w*(-ln(arg))

    // ---- Block reduction: warp shuffle, then cross-warp via shared. ----
    #pragma unroll
    for (int off = 16; off > 0; off >>= 1)
        acc += __shfl_down_sync(FULLM, acc, off);

    __shared__ float swarp[NTHR / 32];
    if (lane == 0) swarp[warp] = acc;
    __syncthreads();
    if (tid == 0) {
        float v = 0.0f;
        #pragma unroll
        for (int i = 0; i < NTHR / 32; ++i) v += swarp[i];
        g_partials[blockIdx.x] = v;
    }

    // ---- Last-block fused finalize (deterministic order). ----
    __shared__ bool s_last;
    __threadfence();
    if (tid == 0) {
        unsigned int old = atomicAdd(&g_ticket, 1u);
        s_last = (old == NBLK - 1);
    }
    __syncthreads();

    if (s_last) {
        __shared__ double sd[NTHR];
        double s = 0.0;
        for (int i = tid; i < NBLK; i += NTHR)   // fixed order per thread
            s += (double)g_partials[i];
        sd[tid] = s;
        __syncthreads();
        #pragma unroll
        for (int stride = NTHR / 2; stride > 0; stride >>= 1) {
            if (tid < stride) sd[tid] += sd[tid + stride];
            __syncthreads();
        }
        if (tid == 0) {
            out[0] = (float)(sd[0] / (double)((size_t)Bd * Hd * Wd));
            g_ticket = 0;                        // reset for next launch/replay
        }
    }
}

extern "C" void kernel_launch(void* const* d_in, const int* in_sizes, int n_in,
                              void* d_out, int out_size)
{
    (void)in_sizes; (void)n_in; (void)out_size;
    const float* pred   = (const float*)d_in[0];
    const float* target = (const float*)d_in[1];
    float* out = (float*)d_out;

    bab_fused<<<NBLK, NTHR>>>(pred, target, out);
}

// round 12
// speedup vs baseline: 1.2946x; 1.0006x over previous
#include <cuda_runtime.h>
#include <math.h>

// Problem shape (fixed by setup_inputs): pred/target (32,1,1024,1024) f32.
#define Wd   1024
#define Hd   1024
#define Bd   32
#define RPB  16                       // rows per block (R8-proven granularity)
#define GRPS (Hd / RPB)               // 64 row-groups per image
#define NBLK (Bd * GRPS)              // 2048 blocks
#define NTHR 256                      // 8 warps * 128 cols = 1024 cols

#define FULLM 0xFFFFFFFFu
#define NLN2  (-0.69314718055994530942f)

__device__ float        g_partials[NBLK];
__device__ unsigned int g_ticket;     // zero-init; reset by last block

__device__ __forceinline__ float4 ldv(const float* p) {
    return *reinterpret_cast<const float4*>(p);
}

// Per-row contribution: Sum_i w_i * log2(1-|t_i-p_i|), w_i = 1+2*b_i.
// Binary mask: 3x3-window sum S in [0,9]; boundary b = min(S, 9-S, 1).
// Border rows/cols handled by DUPLICATING the edge cell (clamp), which
// preserves S==0 <=> all-zero and S==9 <=> all-one exactly.
// haloSum: vertical 3-sum of this lane's halo column (lane 0 = left neighbor
// col, lane 31 = right neighbor col). The halo ADDRESS is clamped into the
// image, so at the image border haloSum equals the thread's own edge colsum
// (exactly the duplicate-edge identity) -> no select needed.
__device__ __forceinline__ float row_loss(
    const float4 c, const float4 t, const float4 p,
    float haloSum, int lane)
{
    float l = __shfl_up_sync(FULLM, c.w, 1);
    float r = __shfl_down_sync(FULLM, c.x, 1);
    if (lane == 0)  l = haloSum;
    if (lane == 31) r = haloSum;

    const float S0 = l   + c.x + c.y;
    const float S1 = c.x + c.y + c.z;
    const float S2 = c.y + c.z + c.w;
    const float S3 = c.z + c.w + r;

    const float b0 = fminf(fminf(S0, 9.0f - S0), 1.0f);
    const float b1 = fminf(fminf(S1, 9.0f - S1), 1.0f);
    const float b2 = fminf(fminf(S2, 9.0f - S2), 1.0f);
    const float b3 = fminf(fminf(S3, 9.0f - S3), 1.0f);

    // arg = 1-|t-p| == (t ? p : 1-p) exactly; pred in (1e-6, 1-1e-6) => arg>0.
    float s;
    s  = fmaf(2.0f, b0, 1.0f) * __log2f(1.0f - fabsf(t.x - p.x));
    s += fmaf(2.0f, b1, 1.0f) * __log2f(1.0f - fabsf(t.y - p.y));
    s += fmaf(2.0f, b2, 1.0f) * __log2f(1.0f - fabsf(t.z - p.z));
    s += fmaf(2.0f, b3, 1.0f) * __log2f(1.0f - fabsf(t.w - p.w));
    return s;
}

__global__ __launch_bounds__(NTHR, 5)
void bab_fused(const float* __restrict__ pred, const float* __restrict__ target,
               float* __restrict__ out)
{
    const int tid  = threadIdx.x;
    const int lane = tid & 31;
    const int warp = tid >> 5;

    const int grp = blockIdx.x;
    const int img = grp / GRPS;
    const int y0  = (grp % GRPS) * RPB;

    const int x0 = warp * 128 + lane * 4;     // this thread's 4 columns

    // Merged halo: lane 0 -> left neighbor col, lane 31 -> right neighbor col.
    // Address clamped into the image: border lanes read their own edge column,
    // which IS the duplicate-edge identity value.
    int xH = (lane == 0) ? (warp * 128 - 1) : (warp * 128 + 128);
    xH = (xH < 0) ? 0 : ((xH > Wd - 1) ? (Wd - 1) : xH);

    const float* __restrict__ tBase = target + (size_t)img * Hd * Wd + (size_t)y0 * Wd;
    const float* __restrict__ pBase = pred   + (size_t)img * Hd * Wd + (size_t)y0 * Wd;

    // Rolling pointers (bumped by 2*Wd per iteration; in-loop offsets are
    // compile-time immediates -> 1 LDG each, no per-load IMAD.WIDE).
    const float* tRow  = tBase + x0;
    const float* pRow  = pBase + x0;
    const float* tHalo = tBase + xH;

    // prev row: y0-1, clamped to y0 at the top border (duplicate row).
    const int prevOff = (y0 > 0) ? -Wd : 0;

    float4 cur  = ldv(tRow);
    float4 prev = ldv(tRow + prevOff);
    float curH  = tHalo[0];
    float prevH = tHalo[prevOff];

    float acc = 0.0f;

    // 7 unconditional 2-row iterations (rows y0..y0+13): y+2 always < Hd here
    // because the only possible clamp is at the very last row of the image.
    #pragma unroll
    for (int it = 0; it < RPB / 2 - 1; ++it) {
        const float4 nextA = ldv(tRow + Wd);
        const float4 nextB = ldv(tRow + 2 * Wd);
        const float4 pA    = ldv(pRow);
        const float4 pB    = ldv(pRow + Wd);
        const float nextAH = tHalo[Wd];
        const float nextBH = tHalo[2 * Wd];

        // Pairwise-shared vertical sums.
        float4 ps;
        ps.x = cur.x + nextA.x;  ps.y = cur.y + nextA.y;
        ps.z = cur.z + nextA.z;  ps.w = cur.w + nextA.w;

        float4 cA, cB;
        cA.x = prev.x + ps.x;  cB.x = ps.x + nextB.x;
        cA.y = prev.y + ps.y;  cB.y = ps.y + nextB.y;
        cA.z = prev.z + ps.z;  cB.z = ps.z + nextB.z;
        cA.w = prev.w + ps.w;  cB.w = ps.w + nextB.w;

        const float hsA = prevH + curH + nextAH;
        const float hsB = curH + nextAH + nextBH;

        acc += row_loss(cA, cur,   pA, hsA, lane);
        acc += row_loss(cB, nextA, pB, hsB, lane);

        prev  = nextA;  cur  = nextB;
        prevH = nextAH; curH = nextBH;

        tRow  += 2 * Wd;
        pRow  += 2 * Wd;
        tHalo += 2 * Wd;
    }

    // Final 2-row iteration (rows y0+14, y0+15): the y+2 row exists unless
    // this is the last row-group of the image; then duplicate the y+1 row.
    {
        const int offB = (y0 + RPB < Hd) ? (2 * Wd) : Wd;

        const float4 nextA = ldv(tRow + Wd);
        const float4 nextB = ldv(tRow + offB);
        const float4 pA    = ldv(pRow);
        const float4 pB    = ldv(pRow + Wd);
        const float nextAH = tHalo[Wd];
        const float nextBH = tHalo[offB];

        float4 ps;
        ps.x = cur.x + nextA.x;  ps.y = cur.y + nextA.y;
        ps.z = cur.z + nextA.z;  ps.w = cur.w + nextA.w;

        float4 cA, cB;
        cA.x = prev.x + ps.x;  cB.x = ps.x + nextB.x;
        cA.y = prev.y + ps.y;  cB.y = ps.y + nextB.y;
        cA.z = prev.z + ps.z;  cB.z = ps.z + nextB.z;
        cA.w = prev.w + ps.w;  cB.w = ps.w + nextB.w;

        const float hsA = prevH + curH + nextAH;
        const float hsB = curH + nextAH + nextBH;

        acc += row_loss(cA, cur,   pA, hsA, lane);
        acc += row_loss(cB, nextA, pB, hsB, lane);
    }

    acc *= NLN2;   // one scale: sum of w*log2(arg) -> sum of w*(-ln(arg))

    // ---- Block reduction: warp shuffle, then cross-warp via shared. ----
    #pragma unroll
    for (int off = 16; off > 0; off >>= 1)
        acc += __shfl_down_sync(FULLM, acc, off);

    __shared__ float swarp[NTHR / 32];
    if (lane == 0) swarp[warp] = acc;
    __syncthreads();
    if (tid == 0) {
        float v = 0.0f;
        #pragma unroll
        for (int i = 0; i < NTHR / 32; ++i) v += swarp[i];
        g_partials[blockIdx.x] = v;
    }

    // ---- Last-block fused finalize (deterministic order). ----
    __shared__ bool s_last;
    __threadfence();
    if (tid == 0) {
        unsigned int old = atomicAdd(&g_ticket, 1u);
        s_last = (old == NBLK - 1);
    }
    __syncthreads();

    if (s_last) {
        __shared__ double sd[NTHR];
        double s = 0.0;
        for (int i = tid; i < NBLK; i += NTHR)   // fixed order per thread
            s += (double)g_partials[i];
        sd[tid] = s;
        __syncthreads();
        #pragma unroll
        for (int stride = NTHR / 2; stride > 0; stride >>= 1) {
            if (tid < stride) sd[tid] += sd[tid + stride];
            __syncthreads();
        }
        if (tid == 0) {
            out[0] = (float)(sd[0] / (double)((size_t)Bd * Hd * Wd));
            g_ticket = 0;                        // reset for next launch/replay
        }
    }
}

extern "C" void kernel_launch(void* const* d_in, const int* in_sizes, int n_in,
                              void* d_out, int out_size)
{
    (void)in_sizes; (void)n_in; (void)out_size;
    const float* pred   = (const float*)d_in[0];
    const float* target = (const float*)d_in[1];
    float* out = (float*)d_out;

    bab_fused<<<NBLK, NTHR>>>(pred, target, out);
}